// round 6
// baseline (speedup 1.0000x reference)
#include <cuda_runtime.h>
#include <cuda_bf16.h>
#include <cstdint>

#define N_NODES 100000
#define N_EDGES 600000
#define D_IN    128
#define D_OUT   96
#define N_REL   4

#define N_TILES  782                 // ceil(100000/128)

#define ROW_BYTES 272                // 128 bf16 (256B) + 16B pad -> conflict-free ldmatrix
#define A_IMG_BYTES (128 * ROW_BYTES)      // 34816
#define B1_ROWS 128
#define B2_ROWS 96
#define B1_IMG_BYTES (B1_ROWS * ROW_BYTES) // 34816
#define B2_IMG_BYTES (B2_ROWS * ROW_BYTES) // 26112

// ---------------- scratch (static device globals; no allocs allowed) --------
__device__ __align__(16) float g_H1[(size_t)N_REL * N_NODES * D_IN];    // 204.8 MB
__device__ __align__(16) float g_out1[(size_t)N_NODES * D_IN];          // 51.2 MB
__device__ __align__(16) float g_H2[(size_t)N_REL * N_NODES * D_OUT];   // 153.6 MB
__device__ int   g_cnt[N_NODES * N_REL];

// weight images (bf16 hi/lo, padded rows). B2 rows 96 only.
__device__ uint4 g_B1hi[5 * (B1_IMG_BYTES / 16)];
__device__ uint4 g_B1lo[5 * (B1_IMG_BYTES / 16)];
__device__ uint4 g_B2hi[5 * (B2_IMG_BYTES / 16)];
__device__ uint4 g_B2lo[5 * (B2_IMG_BYTES / 16)];

// ---------------- helpers ----------------------------------------------------
__device__ __forceinline__ uint32_t smem_u32(const void* p) {
    uint32_t a;
    asm("{ .reg .u64 t; cvta.to.shared.u64 t, %1; cvt.u32.u64 %0, t; }" : "=r"(a) : "l"(p));
    return a;
}

#define LDSM4(r, addr)                                                        \
    asm volatile("ldmatrix.sync.aligned.m8n8.x4.shared.b16 {%0,%1,%2,%3}, [%4];" \
                 : "=r"((r)[0]), "=r"((r)[1]), "=r"((r)[2]), "=r"((r)[3])     \
                 : "r"(addr))

#define MMA16816(d, a, b0, b1)                                                \
    asm volatile("mma.sync.aligned.m16n8k16.row.col.f32.bf16.bf16.f32 "       \
                 "{%0,%1,%2,%3},{%4,%5,%6,%7},{%8,%9},{%0,%1,%2,%3};"         \
                 : "+f"((d)[0]), "+f"((d)[1]), "+f"((d)[2]), "+f"((d)[3])     \
                 : "r"((a)[0]), "r"((a)[1]), "r"((a)[2]), "r"((a)[3]),        \
                   "r"(b0), "r"(b1))

__device__ __forceinline__ uint32_t pack_bf16x2(__nv_bfloat16 a, __nv_bfloat16 b) {
    uint32_t r;
    asm("mov.b32 %0, {%1, %2};" : "=r"(r)
        : "h"(*(unsigned short*)&a), "h"(*(unsigned short*)&b));
    return r;
}

// ---------------- degree counting -------------------------------------------
__global__ void zero_cnt_kernel() {
    int i = blockIdx.x * blockDim.x + threadIdx.x;
    if (i < N_NODES * N_REL) g_cnt[i] = 0;
}
__global__ void count_kernel(const int* __restrict__ ei, const int* __restrict__ et) {
    int e = blockIdx.x * blockDim.x + threadIdx.x;
    if (e < N_EDGES) atomicAdd(&g_cnt[ei[N_EDGES + e] * N_REL + et[e]], 1);
}

// ---------------- weight image prep (Wt[n][k], padded rows) ------------------
__global__ void prep_w1(const float* __restrict__ W, const float* __restrict__ root) {
    int e = blockIdx.x * blockDim.x + threadIdx.x;
    if (e >= 5 * 128 * 128) return;
    int batch = e / 16384, r = e % 16384;
    int k = r / 128, n = r % 128;
    float v = (batch < 4) ? W[(size_t)batch * 16384 + k * 128 + n] : root[k * 128 + n];
    __nv_bfloat16 hi = __float2bfloat16(v);
    __nv_bfloat16 lo = __float2bfloat16(v - __bfloat162float(hi));
    size_t off = (size_t)batch * B1_IMG_BYTES + (size_t)n * ROW_BYTES + (size_t)k * 2;
    *(__nv_bfloat16*)((char*)g_B1hi + off) = hi;
    *(__nv_bfloat16*)((char*)g_B1lo + off) = lo;
}
__global__ void prep_w2(const float* __restrict__ W, const float* __restrict__ root) {
    int e = blockIdx.x * blockDim.x + threadIdx.x;
    if (e >= 5 * 128 * 96) return;
    int batch = e / 12288, r = e % 12288;
    int k = r / 96, n = r % 96;
    float v = (batch < 4) ? W[(size_t)batch * 12288 + k * 96 + n] : root[k * 96 + n];
    __nv_bfloat16 hi = __float2bfloat16(v);
    __nv_bfloat16 lo = __float2bfloat16(v - __bfloat162float(hi));
    size_t off = (size_t)batch * B2_IMG_BYTES + (size_t)n * ROW_BYTES + (size_t)k * 2;
    *(__nv_bfloat16*)((char*)g_B2hi + off) = hi;
    *(__nv_bfloat16*)((char*)g_B2lo + off) = lo;
}

// ---------------- mma.sync GEMM with in-kernel fp32->bf16 hi/lo split --------
// grid = (5 batches, N_TILES); batch 4 = root (+bias).
// CTA 128x128(96) tile, 512 threads, 16 warps 4x4, warp tile 32x32.
// 3-term split in fp32 acc: Ah*Bh + Ah*Bl + Al*Bh.
template <int DOUT, int SRC>   // SRC 0: A = x (ext); 1: A = relu(g_out1)
__global__ __launch_bounds__(512, 1)
void gemm_mma(const float* __restrict__ xext, const float* __restrict__ bias,
              float* __restrict__ out_ext)
{
    constexpr int B_IMG = (DOUT == 128) ? B1_IMG_BYTES : B2_IMG_BYTES;
    constexpr int B_U4  = B_IMG / 16;
    extern __shared__ char smem[];
    char* sAhi = smem;
    char* sAlo = smem + A_IMG_BYTES;
    char* sBhi = smem + 2 * A_IMG_BYTES;
    char* sBlo = smem + 2 * A_IMG_BYTES + B_IMG;

    int tid = threadIdx.x;
    int wid = tid >> 5, lane = tid & 31;
    int batch = blockIdx.x;
    int tile  = blockIdx.y;
    bool isRoot = (batch == 4);

    // ---- stage A: load fp32, split to bf16 hi/lo in registers --------------
    {
        const float* Asrc = (SRC == 0) ? xext : g_out1;
        int row = tid >> 2;             // 0..127
        int kq  = (tid & 3) * 32;       // 32 floats per thread
        int gm  = tile * 128 + row;
        float v[32];
        if (gm < N_NODES) {
            const float4* p = (const float4*)(Asrc + (size_t)gm * 128 + kq);
#pragma unroll
            for (int i = 0; i < 8; i++) {
                float4 f = p[i];
                v[i*4+0] = f.x; v[i*4+1] = f.y; v[i*4+2] = f.z; v[i*4+3] = f.w;
            }
            if (SRC == 1) {
#pragma unroll
                for (int i = 0; i < 32; i++) v[i] = fmaxf(v[i], 0.f);
            }
        } else {
#pragma unroll
            for (int i = 0; i < 32; i++) v[i] = 0.f;
        }
        uint32_t hi[16], lo[16];
#pragma unroll
        for (int i = 0; i < 16; i++) {
            __nv_bfloat16 h0 = __float2bfloat16(v[2*i]);
            __nv_bfloat16 h1 = __float2bfloat16(v[2*i+1]);
            __nv_bfloat16 l0 = __float2bfloat16(v[2*i]   - __bfloat162float(h0));
            __nv_bfloat16 l1 = __float2bfloat16(v[2*i+1] - __bfloat162float(h1));
            hi[i] = pack_bf16x2(h0, h1);
            lo[i] = pack_bf16x2(l0, l1);
        }
        uint4* dh = (uint4*)(sAhi + (size_t)row * ROW_BYTES + kq * 2);
        uint4* dl = (uint4*)(sAlo + (size_t)row * ROW_BYTES + kq * 2);
#pragma unroll
        for (int j = 0; j < 4; j++) {
            dh[j] = *(uint4*)&hi[4*j];
            dl[j] = *(uint4*)&lo[4*j];
        }
    }
    // ---- stage B: flat copies of pre-built images --------------------------
    {
        const uint4* bhi = (DOUT == 128 ? g_B1hi : g_B2hi) + (size_t)batch * B_U4;
        const uint4* blo = (DOUT == 128 ? g_B1lo : g_B2lo) + (size_t)batch * B_U4;
        uint4* s2 = (uint4*)sBhi;
        uint4* s3 = (uint4*)sBlo;
        for (int i = tid; i < B_U4; i += 512) { s2[i] = bhi[i]; s3[i] = blo[i]; }
    }
    __syncthreads();

    int warp_m = (wid & 3) * 32;
    int warp_n = (wid >> 2) * 32;
    if (warp_n >= DOUT) return;    // layer2: n=96 warps have no work (after sync)

    uint32_t sb = smem_u32(smem);
    uint32_t aoff = (uint32_t)(warp_m + (lane & 15)) * ROW_BYTES + ((lane >> 4) & 1) * 16;
    uint32_t boff = (uint32_t)(warp_n + (lane & 7) + ((lane >> 4) & 1) * 8) * ROW_BYTES
                  + ((lane >> 3) & 1) * 16;

    uint32_t aA[2][2], bA[2][2];   // [split][frag]
#pragma unroll
    for (int s = 0; s < 2; s++) {
#pragma unroll
        for (int i = 0; i < 2; i++)
            aA[s][i] = sb + s * A_IMG_BYTES + aoff + i * 16 * ROW_BYTES;
#pragma unroll
        for (int jj = 0; jj < 2; jj++)
            bA[s][jj] = sb + 2 * A_IMG_BYTES + s * B_IMG + boff + jj * 16 * ROW_BYTES;
    }

    float acc[2][4][4];
#pragma unroll
    for (int i = 0; i < 2; i++)
#pragma unroll
        for (int j = 0; j < 4; j++)
#pragma unroll
            for (int q = 0; q < 4; q++) acc[i][j][q] = 0.f;

#pragma unroll
    for (int kk = 0; kk < 8; kk++) {
        uint32_t ah[2][4], al[2][4], bh[2][4], bl[2][4];
#pragma unroll
        for (int i = 0; i < 2; i++) {
            LDSM4(ah[i], aA[0][i]);
            LDSM4(al[i], aA[1][i]);
            aA[0][i] += 32; aA[1][i] += 32;
        }
#pragma unroll
        for (int jj = 0; jj < 2; jj++) {
            LDSM4(bh[jj], bA[0][jj]);
            LDSM4(bl[jj], bA[1][jj]);
            bA[0][jj] += 32; bA[1][jj] += 32;
        }
#pragma unroll
        for (int i = 0; i < 2; i++) {
#pragma unroll
            for (int j = 0; j < 4; j++) {
                int jj = j >> 1, q = (j & 1) * 2;
                MMA16816(acc[i][j], ah[i], bh[jj][q], bh[jj][q + 1]);
                MMA16816(acc[i][j], ah[i], bl[jj][q], bl[jj][q + 1]);
                MMA16816(acc[i][j], al[i], bh[jj][q], bh[jj][q + 1]);
            }
        }
    }

    // ---- epilogue ----------------------------------------------------------
    float* Hbuf = (DOUT == 128) ? g_H1 : g_H2;
    float* Obuf = (DOUT == 128) ? g_out1 : out_ext;
#pragma unroll
    for (int i = 0; i < 2; i++) {
        int row0 = tile * 128 + warp_m + i * 16 + (lane >> 2);
#pragma unroll
        for (int j = 0; j < 4; j++) {
            int col = warp_n + j * 8 + (lane & 3) * 2;
            if (col >= DOUT) continue;
            float2 v0 = make_float2(acc[i][j][0], acc[i][j][1]);
            float2 v1 = make_float2(acc[i][j][2], acc[i][j][3]);
            if (isRoot) {
                float b0 = bias[col], b1 = bias[col + 1];
                v0.x += b0; v0.y += b1; v1.x += b0; v1.y += b1;
            }
            if (row0 < N_NODES) {
                float* dst = isRoot ? (Obuf + (size_t)row0 * DOUT)
                                    : (Hbuf + ((size_t)batch * N_NODES + row0) * DOUT);
                *(float2*)(dst + col) = v0;
            }
            if (row0 + 8 < N_NODES) {
                float* dst = isRoot ? (Obuf + (size_t)(row0 + 8) * DOUT)
                                    : (Hbuf + ((size_t)batch * N_NODES + row0 + 8) * DOUT);
                *(float2*)(dst + col) = v1;
            }
        }
    }
}

// ---------------- edge scatter: one warp per edge, red.global.add.v4 ---------
template <int DOUT>
__global__ void scatter_kernel(const int* __restrict__ ei, const int* __restrict__ et,
                               float* __restrict__ out_ext)
{
    int warp = blockIdx.x * (blockDim.x >> 5) + (threadIdx.x >> 5);
    int lane = threadIdx.x & 31;
    if (warp >= N_EDGES) return;

    const float* H = (DOUT == 128) ? g_H1 : g_H2;
    float* out = (DOUT == 128) ? g_out1 : out_ext;

    int src = ei[warp];
    int dst = ei[N_EDGES + warp];
    int t   = et[warp];
    int c   = g_cnt[dst * N_REL + t];          // 32-lane broadcast, L2-resident
    float nm = 1.0f / (float)(c > 1 ? c : 1);

    if (lane < DOUT / 4) {
        const float4* hp = (const float4*)(H + ((size_t)t * N_NODES + src) * DOUT);
        float4 v = hp[lane];
        float* op = out + (size_t)dst * DOUT + lane * 4;
        asm volatile("red.global.add.v4.f32 [%0], {%1,%2,%3,%4};"
                     :: "l"(op), "f"(v.x * nm), "f"(v.y * nm),
                        "f"(v.z * nm), "f"(v.w * nm)
                     : "memory");
    }
}

// ---------------- launch -----------------------------------------------------
#define SMEM1 (2 * A_IMG_BYTES + 2 * B1_IMG_BYTES)
#define SMEM2 (2 * A_IMG_BYTES + 2 * B2_IMG_BYTES)

extern "C" void kernel_launch(void* const* d_in, const int* in_sizes, int n_in,
                              void* d_out, int out_size)
{
    const float* x     = (const float*)d_in[0];
    const int*   ei    = (const int*)d_in[1];
    const int*   et    = (const int*)d_in[2];
    const float* W1    = (const float*)d_in[3];
    const float* root1 = (const float*)d_in[4];
    const float* b1    = (const float*)d_in[5];
    const float* W2    = (const float*)d_in[6];
    const float* root2 = (const float*)d_in[7];
    const float* b2    = (const float*)d_in[8];
    float* out = (float*)d_out;

    cudaFuncSetAttribute(gemm_mma<128,0>, cudaFuncAttributeMaxDynamicSharedMemorySize, SMEM1);
    cudaFuncSetAttribute(gemm_mma<96,1>,  cudaFuncAttributeMaxDynamicSharedMemorySize, SMEM2);

    zero_cnt_kernel<<<(N_NODES * N_REL + 255) / 256, 256>>>();
    count_kernel<<<(N_EDGES + 255) / 256, 256>>>(ei, et);

    prep_w1<<<(5 * 128 * 128 + 255) / 256, 256>>>(W1, root1);
    prep_w2<<<(5 * 128 * 96 + 255) / 256, 256>>>(W2, root2);

    // layer 1: H1[r] = x@W1[r]; out1 = x@root1 + b1; then scatter into out1
    gemm_mma<128,0><<<dim3(5, N_TILES), 512, SMEM1>>>(x, b1, nullptr);
    scatter_kernel<D_IN><<<(N_EDGES + 7) / 8, 256>>>(ei, et, nullptr);

    // layer 2: A = relu(out1) in-kernel; H2[r] = A@W2[r]; out = A@root2 + b2
    gemm_mma<96,1><<<dim3(5, N_TILES), 512, SMEM2>>>(nullptr, b2, out);
    scatter_kernel<D_OUT><<<(N_EDGES + 7) / 8, 256>>>(ei, et, out);
}

// round 7
// speedup vs baseline: 1.1800x; 1.1800x over previous
#include <cuda_runtime.h>
#include <cuda_bf16.h>
#include <cstdint>

#define N_NODES 100000
#define N_EDGES 600000
#define D_IN    128
#define D_OUT   96
#define N_REL   4

#define N_TILES  782                 // ceil(100000/128)

#define ROW_BYTES 272                // 128 bf16 (256B) + 16B pad -> conflict-free ldmatrix
#define A_IMG_BYTES (128 * ROW_BYTES)      // 34816
#define B1_ROWS 128
#define B2_ROWS 96
#define B1_IMG_BYTES (B1_ROWS * ROW_BYTES) // 34816
#define B2_IMG_BYTES (B2_ROWS * ROW_BYTES) // 26112

// ---------------- scratch (static device globals; no allocs allowed) --------
__device__ __align__(16) float g_H1[(size_t)N_REL * N_NODES * D_IN];    // 204.8 MB
__device__ __align__(16) float g_out1[(size_t)N_NODES * D_IN];          // 51.2 MB
__device__ __align__(16) float g_H2[(size_t)N_REL * N_NODES * D_OUT];   // 153.6 MB
__device__ int   g_cnt[N_NODES * N_REL];

// weight images (bf16 hi/lo, padded rows). B2 rows 96 only.
__device__ uint4 g_B1hi[5 * (B1_IMG_BYTES / 16)];
__device__ uint4 g_B1lo[5 * (B1_IMG_BYTES / 16)];
__device__ uint4 g_B2hi[5 * (B2_IMG_BYTES / 16)];
__device__ uint4 g_B2lo[5 * (B2_IMG_BYTES / 16)];

// ---------------- helpers ----------------------------------------------------
__device__ __forceinline__ uint32_t smem_u32(const void* p) {
    uint32_t a;
    asm("{ .reg .u64 t; cvta.to.shared.u64 t, %1; cvt.u32.u64 %0, t; }" : "=r"(a) : "l"(p));
    return a;
}

#define LDSM4(r, addr)                                                        \
    asm volatile("ldmatrix.sync.aligned.m8n8.x4.shared.b16 {%0,%1,%2,%3}, [%4];" \
                 : "=r"((r)[0]), "=r"((r)[1]), "=r"((r)[2]), "=r"((r)[3])     \
                 : "r"(addr))

#define MMA16816(d, a, b0, b1)                                                \
    asm volatile("mma.sync.aligned.m16n8k16.row.col.f32.bf16.bf16.f32 "       \
                 "{%0,%1,%2,%3},{%4,%5,%6,%7},{%8,%9},{%0,%1,%2,%3};"         \
                 : "+f"((d)[0]), "+f"((d)[1]), "+f"((d)[2]), "+f"((d)[3])     \
                 : "r"((a)[0]), "r"((a)[1]), "r"((a)[2]), "r"((a)[3]),        \
                   "r"(b0), "r"(b1))

__device__ __forceinline__ uint32_t pack_bf16x2(__nv_bfloat16 a, __nv_bfloat16 b) {
    uint32_t r;
    asm("mov.b32 %0, {%1, %2};" : "=r"(r)
        : "h"(*(unsigned short*)&a), "h"(*(unsigned short*)&b));
    return r;
}

// ---------------- degree counting -------------------------------------------
__global__ void zero_cnt_kernel() {
    int i = blockIdx.x * blockDim.x + threadIdx.x;
    if (i < N_NODES * N_REL) g_cnt[i] = 0;
}
__global__ void count_kernel(const int* __restrict__ ei, const int* __restrict__ et) {
    int e = blockIdx.x * blockDim.x + threadIdx.x;
    if (e < N_EDGES) atomicAdd(&g_cnt[ei[N_EDGES + e] * N_REL + et[e]], 1);
}

// ---------------- weight image prep (Wt[n][k], padded rows) ------------------
__global__ void prep_w1(const float* __restrict__ W, const float* __restrict__ root) {
    int e = blockIdx.x * blockDim.x + threadIdx.x;
    if (e >= 5 * 128 * 128) return;
    int batch = e / 16384, r = e % 16384;
    int k = r / 128, n = r % 128;
    float v = (batch < 4) ? W[(size_t)batch * 16384 + k * 128 + n] : root[k * 128 + n];
    __nv_bfloat16 hi = __float2bfloat16(v);
    __nv_bfloat16 lo = __float2bfloat16(v - __bfloat162float(hi));
    size_t off = (size_t)batch * B1_IMG_BYTES + (size_t)n * ROW_BYTES + (size_t)k * 2;
    *(__nv_bfloat16*)((char*)g_B1hi + off) = hi;
    *(__nv_bfloat16*)((char*)g_B1lo + off) = lo;
}
__global__ void prep_w2(const float* __restrict__ W, const float* __restrict__ root) {
    int e = blockIdx.x * blockDim.x + threadIdx.x;
    if (e >= 5 * 128 * 96) return;
    int batch = e / 12288, r = e % 12288;
    int k = r / 96, n = r % 96;
    float v = (batch < 4) ? W[(size_t)batch * 12288 + k * 96 + n] : root[k * 96 + n];
    __nv_bfloat16 hi = __float2bfloat16(v);
    __nv_bfloat16 lo = __float2bfloat16(v - __bfloat162float(hi));
    size_t off = (size_t)batch * B2_IMG_BYTES + (size_t)n * ROW_BYTES + (size_t)k * 2;
    *(__nv_bfloat16*)((char*)g_B2hi + off) = hi;
    *(__nv_bfloat16*)((char*)g_B2lo + off) = lo;
}

// ---------------- fused GEMM: one CTA per tile, loops over all 5 batches -----
// A staged+split ONCE into smem; B images copied per batch (L2-resident).
// CTA 128-row tile, 512 threads, 16 warps 4x4, warp tile 32x32.
// 3-term split in fp32 acc: Ah*Bh + Ah*Bl + Al*Bh.
template <int DOUT, int SRC>   // SRC 0: A = x (ext); 1: A = relu(g_out1)
__global__ __launch_bounds__(512, 1)
void gemm_all(const float* __restrict__ xext, const float* __restrict__ bias,
              float* __restrict__ out_ext)
{
    constexpr int B_IMG = (DOUT == 128) ? B1_IMG_BYTES : B2_IMG_BYTES;
    constexpr int B_U4  = B_IMG / 16;
    extern __shared__ char smem[];
    char* sAhi = smem;
    char* sAlo = smem + A_IMG_BYTES;
    char* sBhi = smem + 2 * A_IMG_BYTES;
    char* sBlo = smem + 2 * A_IMG_BYTES + B_IMG;

    int tid = threadIdx.x;
    int wid = tid >> 5, lane = tid & 31;
    int tile = blockIdx.x;

    // ---- stage A once: load fp32, split to bf16 hi/lo in registers ---------
    {
        const float* Asrc = (SRC == 0) ? xext : g_out1;
        int row = tid >> 2;             // 0..127
        int kq  = (tid & 3) * 32;       // 32 floats per thread
        int gm  = tile * 128 + row;
        float v[32];
        if (gm < N_NODES) {
            const float4* p = (const float4*)(Asrc + (size_t)gm * 128 + kq);
#pragma unroll
            for (int i = 0; i < 8; i++) {
                float4 f = p[i];
                v[i*4+0] = f.x; v[i*4+1] = f.y; v[i*4+2] = f.z; v[i*4+3] = f.w;
            }
            if (SRC == 1) {
#pragma unroll
                for (int i = 0; i < 32; i++) v[i] = fmaxf(v[i], 0.f);
            }
        } else {
#pragma unroll
            for (int i = 0; i < 32; i++) v[i] = 0.f;
        }
        uint32_t hi[16], lo[16];
#pragma unroll
        for (int i = 0; i < 16; i++) {
            __nv_bfloat16 h0 = __float2bfloat16(v[2*i]);
            __nv_bfloat16 h1 = __float2bfloat16(v[2*i+1]);
            __nv_bfloat16 l0 = __float2bfloat16(v[2*i]   - __bfloat162float(h0));
            __nv_bfloat16 l1 = __float2bfloat16(v[2*i+1] - __bfloat162float(h1));
            hi[i] = pack_bf16x2(h0, h1);
            lo[i] = pack_bf16x2(l0, l1);
        }
        uint4* dh = (uint4*)(sAhi + (size_t)row * ROW_BYTES + kq * 2);
        uint4* dl = (uint4*)(sAlo + (size_t)row * ROW_BYTES + kq * 2);
#pragma unroll
        for (int j = 0; j < 4; j++) {
            dh[j] = *(uint4*)&hi[4*j];
            dl[j] = *(uint4*)&lo[4*j];
        }
    }

    int warp_m = (wid & 3) * 32;
    int warp_n = (wid >> 2) * 32;
    bool active = (warp_n < DOUT);

    uint32_t sb = smem_u32(smem);
    uint32_t aoff = (uint32_t)(warp_m + (lane & 15)) * ROW_BYTES + ((lane >> 4) & 1) * 16;
    uint32_t boff = (uint32_t)(warp_n + (lane & 7) + ((lane >> 4) & 1) * 8) * ROW_BYTES
                  + ((lane >> 3) & 1) * 16;

    float* Hbuf = (DOUT == 128) ? g_H1 : g_H2;
    float* Obuf = (DOUT == 128) ? g_out1 : out_ext;

#pragma unroll 1
    for (int batch = 0; batch < 5; batch++) {
        bool isRoot = (batch == 4);
        if (batch > 0) __syncthreads();   // previous MMA done reading B
        // ---- copy B images for this batch (L2-resident) --------------------
        {
            const uint4* bhi = (DOUT == 128 ? g_B1hi : g_B2hi) + (size_t)batch * B_U4;
            const uint4* blo = (DOUT == 128 ? g_B1lo : g_B2lo) + (size_t)batch * B_U4;
            uint4* s2 = (uint4*)sBhi;
            uint4* s3 = (uint4*)sBlo;
            for (int i = tid; i < B_U4; i += 512) { s2[i] = bhi[i]; s3[i] = blo[i]; }
        }
        __syncthreads();                  // B ready (A ready on first iter)

        if (active) {
            uint32_t aA[2][2], bA[2][2];
#pragma unroll
            for (int s = 0; s < 2; s++) {
#pragma unroll
                for (int i = 0; i < 2; i++)
                    aA[s][i] = sb + s * A_IMG_BYTES + aoff + i * 16 * ROW_BYTES;
#pragma unroll
                for (int jj = 0; jj < 2; jj++)
                    bA[s][jj] = sb + 2 * A_IMG_BYTES + s * B_IMG + boff + jj * 16 * ROW_BYTES;
            }

            float acc[2][4][4];
#pragma unroll
            for (int i = 0; i < 2; i++)
#pragma unroll
                for (int j = 0; j < 4; j++)
#pragma unroll
                    for (int q = 0; q < 4; q++) acc[i][j][q] = 0.f;

#pragma unroll
            for (int kk = 0; kk < 8; kk++) {
                uint32_t ah[2][4], al[2][4], bh[2][4], bl[2][4];
#pragma unroll
                for (int i = 0; i < 2; i++) {
                    LDSM4(ah[i], aA[0][i]);
                    LDSM4(al[i], aA[1][i]);
                    aA[0][i] += 32; aA[1][i] += 32;
                }
#pragma unroll
                for (int jj = 0; jj < 2; jj++) {
                    LDSM4(bh[jj], bA[0][jj]);
                    LDSM4(bl[jj], bA[1][jj]);
                    bA[0][jj] += 32; bA[1][jj] += 32;
                }
#pragma unroll
                for (int i = 0; i < 2; i++) {
#pragma unroll
                    for (int j = 0; j < 4; j++) {
                        int jj = j >> 1, q = (j & 1) * 2;
                        MMA16816(acc[i][j], ah[i], bh[jj][q], bh[jj][q + 1]);
                        MMA16816(acc[i][j], ah[i], bl[jj][q], bl[jj][q + 1]);
                        MMA16816(acc[i][j], al[i], bh[jj][q], bh[jj][q + 1]);
                    }
                }
            }

            // ---- epilogue for this batch ----------------------------------
#pragma unroll
            for (int i = 0; i < 2; i++) {
                int row0 = tile * 128 + warp_m + i * 16 + (lane >> 2);
#pragma unroll
                for (int j = 0; j < 4; j++) {
                    int col = warp_n + j * 8 + (lane & 3) * 2;
                    if (col >= DOUT) continue;
                    float2 v0 = make_float2(acc[i][j][0], acc[i][j][1]);
                    float2 v1 = make_float2(acc[i][j][2], acc[i][j][3]);
                    if (isRoot) {
                        float b0 = bias[col], b1 = bias[col + 1];
                        v0.x += b0; v0.y += b1; v1.x += b0; v1.y += b1;
                    }
                    if (row0 < N_NODES) {
                        float* dst = isRoot ? (Obuf + (size_t)row0 * DOUT)
                                            : (Hbuf + ((size_t)batch * N_NODES + row0) * DOUT);
                        *(float2*)(dst + col) = v0;
                    }
                    if (row0 + 8 < N_NODES) {
                        float* dst = isRoot ? (Obuf + (size_t)(row0 + 8) * DOUT)
                                            : (Hbuf + ((size_t)batch * N_NODES + row0 + 8) * DOUT);
                        *(float2*)(dst + col) = v1;
                    }
                }
            }
        }
    }
}

// ---------------- edge scatter: one warp per edge, red.global.add.v4 ---------
template <int DOUT>
__global__ void scatter_kernel(const int* __restrict__ ei, const int* __restrict__ et,
                               float* __restrict__ out_ext)
{
    int warp = blockIdx.x * (blockDim.x >> 5) + (threadIdx.x >> 5);
    int lane = threadIdx.x & 31;
    if (warp >= N_EDGES) return;

    const float* H = (DOUT == 128) ? g_H1 : g_H2;
    float* out = (DOUT == 128) ? g_out1 : out_ext;

    int src = ei[warp];
    int dst = ei[N_EDGES + warp];
    int t   = et[warp];
    int c   = g_cnt[dst * N_REL + t];          // 32-lane broadcast, L2-resident
    float nm = 1.0f / (float)(c > 1 ? c : 1);

    if (lane < DOUT / 4) {
        const float4* hp = (const float4*)(H + ((size_t)t * N_NODES + src) * DOUT);
        float4 v = hp[lane];
        float* op = out + (size_t)dst * DOUT + lane * 4;
        asm volatile("red.global.add.v4.f32 [%0], {%1,%2,%3,%4};"
                     :: "l"(op), "f"(v.x * nm), "f"(v.y * nm),
                        "f"(v.z * nm), "f"(v.w * nm)
                     : "memory");
    }
}

// ---------------- launch -----------------------------------------------------
#define SMEM1 (2 * A_IMG_BYTES + 2 * B1_IMG_BYTES)   // 139264
#define SMEM2 (2 * A_IMG_BYTES + 2 * B2_IMG_BYTES)   // 121856

extern "C" void kernel_launch(void* const* d_in, const int* in_sizes, int n_in,
                              void* d_out, int out_size)
{
    const float* x     = (const float*)d_in[0];
    const int*   ei    = (const int*)d_in[1];
    const int*   et    = (const int*)d_in[2];
    const float* W1    = (const float*)d_in[3];
    const float* root1 = (const float*)d_in[4];
    const float* b1    = (const float*)d_in[5];
    const float* W2    = (const float*)d_in[6];
    const float* root2 = (const float*)d_in[7];
    const float* b2    = (const float*)d_in[8];
    float* out = (float*)d_out;

    cudaFuncSetAttribute(gemm_all<128,0>, cudaFuncAttributeMaxDynamicSharedMemorySize, SMEM1);
    cudaFuncSetAttribute(gemm_all<96,1>,  cudaFuncAttributeMaxDynamicSharedMemorySize, SMEM2);

    zero_cnt_kernel<<<(N_NODES * N_REL + 255) / 256, 256>>>();
    count_kernel<<<(N_EDGES + 255) / 256, 256>>>(ei, et);

    prep_w1<<<(5 * 128 * 128 + 255) / 256, 256>>>(W1, root1);
    prep_w2<<<(5 * 128 * 96 + 255) / 256, 256>>>(W2, root2);

    // layer 1: H1[r] = x@W1[r]; out1 = x@root1 + b1; then scatter into out1
    gemm_all<128,0><<<N_TILES, 512, SMEM1>>>(x, b1, nullptr);
    scatter_kernel<D_IN><<<(N_EDGES + 7) / 8, 256>>>(ei, et, nullptr);

    // layer 2: A = relu(out1) in-kernel; H2[r] = A@W2[r]; out = A@root2 + b2
    gemm_all<96,1><<<N_TILES, 512, SMEM2>>>(nullptr, b2, out);
    scatter_kernel<D_OUT><<<(N_EDGES + 7) / 8, 256>>>(ei, et, out);
}